// round 1
// baseline (speedup 1.0000x reference)
#include <cuda_runtime.h>
#include <math.h>

// ---------------------------------------------------------------------------
// CueWordSelectNet: 2-layer LSTM scan (T=64) + topic scatter + 2 linears +
// softmax over batch dim.
//
// Weight prep (per launch, inside graph):
//   Wc1 [1600 x 4000]: rows 0..599  = W_ih1[:, :600]^T   (x_t part)
//                      rows 600..   = (W_ih1[:,600:1600] + W_hh1)^T
//   Wc2 [2000 x 4000]: rows 0..999  = W_ih2[:,600:1600]^T  (h1 part)
//                      rows 1000..  = (W_ih2[:,1600:2600] + W_hh2)^T
//   Gate columns permuted: n = 4*u + g  (g: 0=i,1=f,2=g,3=o), so each GEMM
//   thread (4 adjacent cols) owns a full hidden unit -> fused LSTM epilogue.
// ---------------------------------------------------------------------------

#define BATCH   256
#define TSTEPS  64
#define INSZ    600
#define HID     1000
#define GATES   4000

#define BM 128
#define BN 64
#define BKK 16

// ----- scratch layout (floats) ---------------------------------------------
#define OFF_WC1   0                         // 1600*4000 = 6,400,000
#define OFF_WC2   6400000                   // 2000*4000 = 8,000,000
#define OFF_WT1   14400000                  // 2000*4000 = 8,000,000
#define OFF_WT2   22400000                  // 4000*1000 = 4,000,000
#define OFF_BC1   26400000                  // 4000
#define OFF_BC2   26404000                  // 4000
#define OFF_ZERO  26408000                  // zeroed region start
#define OFF_H1A   26408000                  // 256,000
#define OFF_H2A   26664000                  // 256,000
#define OFF_C1    26920000                  // 256,000
#define OFF_C2    27176000                  // 256,000
#define OFF_TOPIC 27432000                  // 256,000   (end of zero region)
#define OFF_H1B   27688000                  // 256,000
#define OFF_H2B   27944000                  // 256,000
#define OFF_M1    28200000                  // 256*4000 = 1,024,000
#define OFF_M2    29224000                  // 256,000
#define SCRATCH_TOTAL 29480000

__device__ float g_scratch[SCRATCH_TOTAL];

__device__ __forceinline__ float sigmoidf_(float x) {
    return 1.0f / (1.0f + expf(-x));
}

// ---------------------------------------------------------------------------
// GEMM: C[256 x N] = A[256 x K] * B[K x N], A read from two row-segments
// (k < split -> A1, else A2). EPI=1: fused LSTM cell; EPI=0: bias add + store.
// ---------------------------------------------------------------------------
template <int EPI>
__global__ __launch_bounds__(256)
void gemm_k(const float* __restrict__ A1, int lda1, int split,
            const float* __restrict__ A2, int lda2,
            const float* __restrict__ Bm, int K, int N,
            const float* __restrict__ bias,
            float* __restrict__ outp,
            float* __restrict__ cbuf,
            float* __restrict__ hbuf)
{
    __shared__ __align__(16) float As[BKK][BM];
    __shared__ __align__(16) float Bs[BKK][BN];

    const int tid = threadIdx.x;
    const int tx = tid & 15;    // 16 col-groups of 4
    const int ty = tid >> 4;    // 16 row-groups of 8
    const int rowBase = blockIdx.y * BM;
    const int colBase = blockIdx.x * BN;

    float acc[8][4];
#pragma unroll
    for (int i = 0; i < 8; i++)
#pragma unroll
        for (int j = 0; j < 4; j++) acc[i][j] = 0.0f;

    for (int k0 = 0; k0 < K; k0 += BKK) {
        // A tile: 128 rows x 16 k  (2048 elems, 8 per thread)
#pragma unroll
        for (int i = 0; i < 8; i++) {
            int idx = tid + i * 256;
            int m  = idx >> 4;
            int kk = idx & 15;
            int gk = k0 + kk;
            int grow = rowBase + m;
            float v;
            if (gk < split) v = A1[grow * lda1 + gk];
            else            v = A2[grow * lda2 + (gk - split)];
            As[kk][m] = v;
        }
        // B tile: 16 k x 64 cols (1024 elems, 4 per thread), fully coalesced
#pragma unroll
        for (int i = 0; i < 4; i++) {
            int idx = tid + i * 256;
            int kk = idx >> 6;
            int n  = idx & 63;
            int gcol = colBase + n;
            Bs[kk][n] = (gcol < N) ? Bm[(k0 + kk) * N + gcol] : 0.0f;
        }
        __syncthreads();

#pragma unroll
        for (int kk = 0; kk < BKK; kk++) {
            float4 b4 = *reinterpret_cast<const float4*>(&Bs[kk][tx * 4]);
            float4 a0 = *reinterpret_cast<const float4*>(&As[kk][ty * 8]);
            float4 a1 = *reinterpret_cast<const float4*>(&As[kk][ty * 8 + 4]);
            float a[8] = {a0.x, a0.y, a0.z, a0.w, a1.x, a1.y, a1.z, a1.w};
            float b[4] = {b4.x, b4.y, b4.z, b4.w};
#pragma unroll
            for (int i = 0; i < 8; i++)
#pragma unroll
                for (int j = 0; j < 4; j++)
                    acc[i][j] = fmaf(a[i], b[j], acc[i][j]);
        }
        __syncthreads();
    }

    if (EPI == 1) {
        // LSTM epilogue: this thread's 4 cols = one hidden unit (i,f,g,o)
        int u = blockIdx.x * 16 + tx;
        if (u < HID) {
            float bi = bias[4 * u + 0];
            float bf = bias[4 * u + 1];
            float bg = bias[4 * u + 2];
            float bo = bias[4 * u + 3];
#pragma unroll
            for (int i = 0; i < 8; i++) {
                int row = rowBase + ty * 8 + i;
                float iv = sigmoidf_(acc[i][0] + bi);
                float fv = sigmoidf_(acc[i][1] + bf);
                float gv = tanhf    (acc[i][2] + bg);
                float ov = sigmoidf_(acc[i][3] + bo);
                float cn = fv * cbuf[row * HID + u] + iv * gv;
                cbuf[row * HID + u] = cn;
                hbuf[row * HID + u] = ov * tanhf(cn);
            }
        }
    } else {
#pragma unroll
        for (int i = 0; i < 8; i++) {
            int row = rowBase + ty * 8 + i;
#pragma unroll
            for (int j = 0; j < 4; j++) {
                int col = colBase + tx * 4 + j;
                if (col < N) outp[row * N + col] = acc[i][j] + bias[col];
            }
        }
    }
}

// ---------------------------------------------------------------------------
// Weight prep kernels
// ---------------------------------------------------------------------------
__global__ void prep_wc1_k(const float* __restrict__ Wih,
                           const float* __restrict__ Whh,
                           float* __restrict__ Wc)
{
    int idx = blockIdx.x * blockDim.x + threadIdx.x;
    if (idx >= 1600 * GATES) return;
    int k = idx / GATES;
    int n = idx - k * GATES;
    int u = n >> 2, g = n & 3;
    int r = g * HID + u;
    float v = Wih[r * 1600 + k];
    if (k >= INSZ) v += Whh[r * HID + (k - INSZ)];
    Wc[idx] = v;
}

__global__ void prep_wc2_k(const float* __restrict__ Wih,
                           const float* __restrict__ Whh,
                           float* __restrict__ Wc)
{
    int idx = blockIdx.x * blockDim.x + threadIdx.x;
    if (idx >= 2000 * GATES) return;
    int k = idx / GATES;
    int n = idx - k * GATES;
    int u = n >> 2, g = n & 3;
    int r = g * HID + u;
    float v = Wih[r * 2600 + 600 + k];          // cols 600..2599 of W_ih2
    if (k >= 1000) v += Whh[r * HID + (k - 1000)];
    Wc[idx] = v;
}

__global__ void prep_bias_k(const float* __restrict__ bi,
                            const float* __restrict__ bh,
                            float* __restrict__ bc)
{
    int n = blockIdx.x * blockDim.x + threadIdx.x;
    if (n >= GATES) return;
    int u = n >> 2, g = n & 3;
    int r = g * HID + u;
    bc[n] = bi[r] + bh[r];
}

// W [Rw x Cw] row-major  ->  Wt [Cw x Rw]
__global__ void prep_wt_k(const float* __restrict__ W,
                          float* __restrict__ Wt, int Rw, int Cw)
{
    int idx = blockIdx.x * blockDim.x + threadIdx.x;
    if (idx >= Rw * Cw) return;
    int k = idx / Rw;          // 0..Cw-1
    int n = idx - k * Rw;      // 0..Rw-1
    Wt[idx] = W[n * Cw + k];
}

__global__ void topic_k(const int* __restrict__ h, float* __restrict__ topic)
{
    int tid = blockIdx.x * blockDim.x + threadIdx.x;
    if (tid >= BATCH * 5) return;
    int b = tid / 5;
    int hv = h[tid];
    topic[b * HID + hv] = 1.0f;
}

// softmax over the BATCH dimension (axis 0): one block per column
__global__ void softmax_col_k(const float* __restrict__ m, float* __restrict__ outp)
{
    __shared__ float red[256];
    int col = blockIdx.x;
    int tid = threadIdx.x;
    float v = m[tid * HID + col];
    red[tid] = v;
    __syncthreads();
    for (int s = 128; s > 0; s >>= 1) {
        if (tid < s) red[tid] = fmaxf(red[tid], red[tid + s]);
        __syncthreads();
    }
    float mx = red[0];
    __syncthreads();
    float e = expf(v - mx);
    red[tid] = e;
    __syncthreads();
    for (int s = 128; s > 0; s >>= 1) {
        if (tid < s) red[tid] += red[tid + s];
        __syncthreads();
    }
    float sum = red[0];
    outp[tid * HID + col] = e / sum;
}

__global__ void copy4_k(const float* __restrict__ h1, const float* __restrict__ c1,
                        const float* __restrict__ h2, const float* __restrict__ c2,
                        float* __restrict__ outp)
{
    int idx = blockIdx.x * blockDim.x + threadIdx.x;
    const int SZ = BATCH * HID;
    if (idx >= 4 * SZ) return;
    int sec = idx / SZ;
    int off = idx - sec * SZ;
    const float* src = (sec == 0) ? h1 : (sec == 1) ? c1 : (sec == 2) ? h2 : c2;
    outp[idx] = src[off];
}

// ---------------------------------------------------------------------------
extern "C" void kernel_launch(void* const* d_in, const int* in_sizes, int n_in,
                              void* d_out, int out_size)
{
    const float* input = (const float*)d_in[0];
    const int*   hidx  = (const int*)d_in[1];
    const float* W_ih1 = (const float*)d_in[2];
    const float* W_hh1 = (const float*)d_in[3];
    const float* b_ih1 = (const float*)d_in[4];
    const float* b_hh1 = (const float*)d_in[5];
    const float* W_ih2 = (const float*)d_in[6];
    const float* W_hh2 = (const float*)d_in[7];
    const float* b_ih2 = (const float*)d_in[8];
    const float* b_hh2 = (const float*)d_in[9];
    const float* W1    = (const float*)d_in[10];
    const float* b1    = (const float*)d_in[11];
    const float* W2    = (const float*)d_in[12];
    const float* b2    = (const float*)d_in[13];
    float* outp = (float*)d_out;

    float* S = nullptr;
    cudaGetSymbolAddress((void**)&S, g_scratch);

    float* Wc1   = S + OFF_WC1;
    float* Wc2   = S + OFF_WC2;
    float* Wt1   = S + OFF_WT1;
    float* Wt2   = S + OFF_WT2;
    float* bc1   = S + OFF_BC1;
    float* bc2   = S + OFF_BC2;
    float* c1    = S + OFF_C1;
    float* c2    = S + OFF_C2;
    float* topic = S + OFF_TOPIC;
    float* m1    = S + OFF_M1;
    float* m2    = S + OFF_M2;
    float* h1b[2] = { S + OFF_H1A, S + OFF_H1B };
    float* h2b[2] = { S + OFF_H2A, S + OFF_H2B };

    // ---- prep (cheap, fully parallel) ----
    prep_wc1_k<<<(1600 * GATES + 255) / 256, 256>>>(W_ih1, W_hh1, Wc1);
    prep_wc2_k<<<(2000 * GATES + 255) / 256, 256>>>(W_ih2, W_hh2, Wc2);
    prep_wt_k <<<(2000 * GATES + 255) / 256, 256>>>(W1, Wt1, GATES, 2000);
    prep_wt_k <<<(4000 * HID   + 255) / 256, 256>>>(W2, Wt2, HID, GATES);
    prep_bias_k<<<(GATES + 255) / 256, 256>>>(b_ih1, b_hh1, bc1);
    prep_bias_k<<<(GATES + 255) / 256, 256>>>(b_ih2, b_hh2, bc2);
    cudaMemsetAsync(S + OFF_ZERO, 0, (size_t)5 * BATCH * HID * sizeof(float), 0);

    dim3 blk(256);
    dim3 gridG((GATES + BN - 1) / BN, BATCH / BM);   // 63 x 2
    dim3 gridH((HID   + BN - 1) / BN, BATCH / BM);   // 16 x 2

    // ---- sequential scan over T ----
    int cur = 0;
    for (int t = 0; t < TSTEPS; t++) {
        // LSTM1: A = [x_t (600) | h1_old (1000)], fused LSTM epilogue
        gemm_k<1><<<gridG, blk>>>(input + t * INSZ, TSTEPS * INSZ, INSZ,
                                  h1b[cur], HID,
                                  Wc1, 1600, GATES,
                                  bc1, nullptr, c1, h1b[1 - cur]);
        // LSTM2: A = [h1_new (1000) | h2_old (1000)]
        gemm_k<1><<<gridG, blk>>>(h1b[1 - cur], HID, HID,
                                  h2b[cur], HID,
                                  Wc2, 2000, GATES,
                                  bc2, nullptr, c2, h2b[1 - cur]);
        cur ^= 1;
    }
    // 64 iterations: final state lives in index 0 == cur

    // ---- head: topic scatter + 2 linears + batch-softmax ----
    topic_k<<<(BATCH * 5 + 255) / 256, 256>>>(hidx, topic);
    gemm_k<0><<<gridG, blk>>>(h1b[cur], HID, HID, topic, HID,
                              Wt1, 2000, GATES, b1, m1, nullptr, nullptr);
    gemm_k<0><<<gridH, blk>>>(m1, GATES, GATES, m1, GATES,
                              Wt2, GATES, HID, b2, m2, nullptr, nullptr);
    softmax_col_k<<<HID, 256>>>(m2, outp);

    // ---- tail outputs: (h1,c1),(h2,c2) if the harness expects them ----
    if (out_size >= 5 * BATCH * HID) {
        copy4_k<<<(4 * BATCH * HID + 255) / 256, 256>>>(
            h1b[cur], c1, h2b[cur], c2, outp + BATCH * HID);
    }
}

// round 3
// speedup vs baseline: 4.0262x; 4.0262x over previous
#include <cuda_runtime.h>
#include <math.h>
#include <stdint.h>

// ---------------------------------------------------------------------------
// CueWordSelectNet on TF32 tensor cores (mma.sync m16n8k8).
//
//  - XP = X @ Wx1 precomputed for all T (parallel GEMM, M=16384)
//  - per step: gates1 = h1 @ Wh1 (K=1024 padded) + XP[t] + b  -> LSTM -> h1,c1
//              gates2 = [h1|pad|h2|pad] @ Wc2 (K=2048)  + b  -> LSTM -> h2,c2
//  - state kept in padded concat buffers (stride 2048), ping-pong
//  - gate cols permuted so one mma thread owns a full hidden unit:
//      col(u,g) = (u>>3)*32 + (g>=2)*16 + ((u>>2)&1)*8 + 2*(u&3) + (g&1)
//  - head: hcat=[h1|pad|topic|pad] @ Wt1 -> m1 @ Wt2 -> softmax(axis=0)
// ---------------------------------------------------------------------------

#define BATCH   256
#define TSTEPS  64
#define INSZ    600
#define HID     1000
#define NP      4032          // padded gate/linear1 width (63 * 64)
#define NP2     1024          // padded linear2 width
#define KCAT    2048          // padded concat K
#define KH1     1024          // padded h1-only K
#define KX      608           // padded input K
#define LD_XP   (TSTEPS * NP) // 258048

#define BM 128
#define BN 64
#define BK 32
#define BKP 36
#define BNP 72
#define SMEM_FLOATS (2 * (BM * BKP + BK * BNP))   // 13824
#define SMEM_BYTES  (SMEM_FLOATS * 4)             // 55296

// ----- scratch layout (floats) ---------------------------------------------
#define OFF_WX1   0ll                        // 608*4032   = 2,451,456
#define OFF_WH1   2451456ll                  // 1024*4032  = 4,128,768
#define OFF_WC2   6580224ll                  // 2048*4032  = 8,257,536
#define OFF_WT1   14837760ll                 // 2048*4032  = 8,257,536
#define OFF_WT2   23095296ll                 // 4032*1024  = 4,128,768
#define OFF_BC1   27224064ll                 // 4032
#define OFF_BC2   27228096ll                 // 4032
#define OFF_B1P   27232128ll                 // 4032
#define OFF_B2P   27236160ll                 // 1024
#define OFF_XP    27237184ll                 // 16384*4032 = 66,060,288
// ---- zeroed-every-launch region ----
#define OFF_ZB    93297472ll                 // 4032 (zero bias)
#define OFF_CAT0  93301504ll                 // 256*2048 = 524,288
#define OFF_CAT1  93825792ll                 // 524,288
#define OFF_C1    94350080ll                 // 256,000
#define OFF_C2    94606080ll                 // 256,000
#define OFF_HCAT  94862080ll                 // 524,288
#define ZERO_CNT  (95386368ll - 93297472ll)  // 2,088,896
// ---- end zero region ----
#define OFF_M1    95386368ll                 // 256*4032 = 1,032,192
#define OFF_M2    96418560ll                 // 256,000
#define SCRATCH_TOTAL 96674560ll

__device__ __align__(256) float g_scratch[SCRATCH_TOTAL];

__device__ __forceinline__ float sigmoidf_(float x) {
    return 1.0f / (1.0f + expf(-x));
}
__device__ __forceinline__ float to_tf32(float x) {
    uint32_t r;
    asm("cvt.rna.tf32.f32 %0, %1;" : "=r"(r) : "f"(x));
    return __uint_as_float(r);
}
__device__ __forceinline__ uint32_t to_tf32u(float x) {
    uint32_t r;
    asm("cvt.rna.tf32.f32 %0, %1;" : "=r"(r) : "f"(x));
    return r;
}
__device__ __forceinline__ void mma_tf32(float* c, const uint32_t* a, const uint32_t* b) {
    asm volatile(
        "mma.sync.aligned.m16n8k8.row.col.f32.tf32.tf32.f32 "
        "{%0,%1,%2,%3}, {%4,%5,%6,%7}, {%8,%9}, {%0,%1,%2,%3};"
        : "+f"(c[0]), "+f"(c[1]), "+f"(c[2]), "+f"(c[3])
        : "r"(a[0]), "r"(a[1]), "r"(a[2]), "r"(a[3]), "r"(b[0]), "r"(b[1]));
}
__device__ __forceinline__ void cp16(uint32_t dst, const float* src, bool pred) {
    asm volatile("cp.async.cg.shared.global [%0], [%1], 16, %2;"
                 :: "r"(dst), "l"(src), "r"(pred ? 16 : 0));
}
__device__ __forceinline__ void cp_commit() {
    asm volatile("cp.async.commit_group;");
}
template <int N>
__device__ __forceinline__ void cp_wait() {
    asm volatile("cp.async.wait_group %0;" :: "n"(N));
}

// ---------------------------------------------------------------------------
// TF32 GEMM: C[M x NP] = A[M x K] * B[K x NP]
// EPI=1: fused LSTM (optional xp add); EPI=0: bias add + store.
// ---------------------------------------------------------------------------
template <int EPI>
__global__ __launch_bounds__(256)
void gemm_tf32(const float* __restrict__ A, int lda, int kValid, int K,
               const float* __restrict__ B, int ldb,
               const float* __restrict__ bias,
               const float* __restrict__ xp, int ldxp,
               float* __restrict__ outp, int ldout, int ncols,
               float* __restrict__ cbuf, float* __restrict__ hbuf, int hstride)
{
    extern __shared__ float sm[];
    float* AsB = sm;                    // 2 * BM*BKP
    float* BsB = sm + 2 * BM * BKP;     // 2 * BK*BNP

    const int tid = threadIdx.x;
    const int warp = tid >> 5;
    const int lane = tid & 31;
    const int gid = lane >> 2;
    const int tig = lane & 3;
    const int wm = (warp >> 1) * 32;
    const int wn = (warp & 1) * 32;
    const int rowBase = blockIdx.y * BM;
    const int colBase = blockIdx.x * BN;

    float acc[2][4][4];
#pragma unroll
    for (int a = 0; a < 2; a++)
#pragma unroll
        for (int b = 0; b < 4; b++)
#pragma unroll
            for (int c = 0; c < 4; c++) acc[a][b][c] = 0.0f;

    const int nIters = K / BK;

    // ---- stage tile 0 ----
    {
        const int k0 = 0;
#pragma unroll
        for (int i = 0; i < 4; i++) {
            int slot = tid + i * 256;
            int m = slot >> 3, kq = slot & 7;
            int k = k0 + kq * 4;
            bool p = k < kValid;
            const float* src = A + (size_t)(rowBase + m) * lda + k;
            uint32_t dst = (uint32_t)__cvta_generic_to_shared(AsB + m * BKP + kq * 4);
            cp16(dst, p ? src : A, p);
        }
#pragma unroll
        for (int i = 0; i < 2; i++) {
            int slot = tid + i * 256;
            int kk = slot >> 4, nq = slot & 15;
            const float* src = B + (size_t)(k0 + kk) * ldb + colBase + nq * 4;
            uint32_t dst = (uint32_t)__cvta_generic_to_shared(BsB + kk * BNP + nq * 4);
            cp16(dst, src, true);
        }
        cp_commit();
    }

    int buf = 0;
    for (int kt = 0; kt < nIters; kt++) {
        if (kt + 1 < nIters) {
            const int k0 = (kt + 1) * BK;
            float* Asn = AsB + (buf ^ 1) * BM * BKP;
            float* Bsn = BsB + (buf ^ 1) * BK * BNP;
#pragma unroll
            for (int i = 0; i < 4; i++) {
                int slot = tid + i * 256;
                int m = slot >> 3, kq = slot & 7;
                int k = k0 + kq * 4;
                bool p = k < kValid;
                const float* src = A + (size_t)(rowBase + m) * lda + k;
                uint32_t dst = (uint32_t)__cvta_generic_to_shared(Asn + m * BKP + kq * 4);
                cp16(dst, p ? src : A, p);
            }
#pragma unroll
            for (int i = 0; i < 2; i++) {
                int slot = tid + i * 256;
                int kk = slot >> 4, nq = slot & 15;
                const float* src = B + (size_t)(k0 + kk) * ldb + colBase + nq * 4;
                uint32_t dst = (uint32_t)__cvta_generic_to_shared(Bsn + kk * BNP + nq * 4);
                cp16(dst, src, true);
            }
        }
        cp_commit();
        cp_wait<1>();
        __syncthreads();

        const float* Ab = AsB + buf * BM * BKP;
        const float* Bb = BsB + buf * BK * BNP;
#pragma unroll
        for (int kk = 0; kk < 4; kk++) {
            const int kb = kk * 8;
            uint32_t af[2][4];
#pragma unroll
            for (int mi = 0; mi < 2; mi++) {
                const float* ap = Ab + (wm + mi * 16 + gid) * BKP + kb + tig;
                af[mi][0] = to_tf32u(ap[0]);
                af[mi][1] = to_tf32u(ap[8 * BKP]);
                af[mi][2] = to_tf32u(ap[4]);
                af[mi][3] = to_tf32u(ap[8 * BKP + 4]);
            }
            uint32_t bf[4][2];
#pragma unroll
            for (int j = 0; j < 4; j++) {
                const float* bp = Bb + (kb + tig) * BNP + wn + j * 8 + gid;
                bf[j][0] = __float_as_uint(bp[0]);
                bf[j][1] = __float_as_uint(bp[4 * BNP]);
            }
#pragma unroll
            for (int mi = 0; mi < 2; mi++)
#pragma unroll
                for (int j = 0; j < 4; j++)
                    mma_tf32(acc[mi][j], af[mi], bf[j]);
        }
        __syncthreads();
        buf ^= 1;
    }

    const int g32 = colBase + wn;

    if (EPI == 1) {
        const int group = g32 >> 5;
        if (group < 125) {
            float2 bAif = *(const float2*)(bias + g32 + 2 * tig);
            float2 bBif = *(const float2*)(bias + g32 + 8 + 2 * tig);
            float2 bAgo = *(const float2*)(bias + g32 + 16 + 2 * tig);
            float2 bBgo = *(const float2*)(bias + g32 + 24 + 2 * tig);
            const int uA = group * 8 + tig;
            const int uB = uA + 4;
#pragma unroll
            for (int mi = 0; mi < 2; mi++) {
#pragma unroll
                for (int rh = 0; rh < 2; rh++) {
                    int row = rowBase + wm + mi * 16 + rh * 8 + gid;
                    float2 v0 = make_float2(0.f, 0.f), v1 = v0, v2 = v0, v3 = v0;
                    if (xp) {
                        const float* xr = xp + (size_t)row * ldxp + g32 + 2 * tig;
                        v0 = *(const float2*)(xr);
                        v1 = *(const float2*)(xr + 8);
                        v2 = *(const float2*)(xr + 16);
                        v3 = *(const float2*)(xr + 24);
                    }
                    int r0 = rh * 2, r1 = rh * 2 + 1;
                    // unit A
                    {
                        float iv = sigmoidf_(acc[mi][0][r0] + bAif.x + v0.x);
                        float fv = sigmoidf_(acc[mi][0][r1] + bAif.y + v0.y);
                        float gv = tanhf    (acc[mi][2][r0] + bAgo.x + v2.x);
                        float ov = sigmoidf_(acc[mi][2][r1] + bAgo.y + v2.y);
                        float cn = fv * cbuf[row * HID + uA] + iv * gv;
                        cbuf[row * HID + uA] = cn;
                        hbuf[(size_t)row * hstride + uA] = ov * tanhf(cn);
                    }
                    // unit B
                    {
                        float iv = sigmoidf_(acc[mi][1][r0] + bBif.x + v1.x);
                        float fv = sigmoidf_(acc[mi][1][r1] + bBif.y + v1.y);
                        float gv = tanhf    (acc[mi][3][r0] + bBgo.x + v3.x);
                        float ov = sigmoidf_(acc[mi][3][r1] + bBgo.y + v3.y);
                        float cn = fv * cbuf[row * HID + uB] + iv * gv;
                        cbuf[row * HID + uB] = cn;
                        hbuf[(size_t)row * hstride + uB] = ov * tanhf(cn);
                    }
                }
            }
        }
    } else {
#pragma unroll
        for (int mi = 0; mi < 2; mi++)
#pragma unroll
            for (int rh = 0; rh < 2; rh++) {
                int row = rowBase + wm + mi * 16 + rh * 8 + gid;
#pragma unroll
                for (int j = 0; j < 4; j++) {
                    int col = g32 + j * 8 + 2 * tig;
                    if (col < ncols) {
                        float2 v;
                        v.x = acc[mi][j][rh * 2] + bias[col];
                        v.y = acc[mi][j][rh * 2 + 1] + bias[col + 1];
                        *(float2*)(outp + (size_t)row * ldout + col) = v;
                    }
                }
            }
    }
}

// ---------------------------------------------------------------------------
// Prep kernels. Gate col mapping: col(u,g) computed inverse here.
// n -> (u,g): group=n>>5, gh=(n>>4)&1, half=(n>>3)&1, jj=(n>>1)&3, gl=n&1
//             u = group*8 + half*4 + jj ; g = gh*2 + gl
// ---------------------------------------------------------------------------
__device__ __forceinline__ void decode_gate(int n, int& u, int& g) {
    int group = n >> 5;
    int gh = (n >> 4) & 1;
    int half = (n >> 3) & 1;
    int jj = (n >> 1) & 3;
    int gl = n & 1;
    u = group * 8 + half * 4 + jj;
    g = gh * 2 + gl;
}

__global__ void prep_wx1_k(const float* __restrict__ Wih, float* __restrict__ W) {
    long long idx = (long long)blockIdx.x * blockDim.x + threadIdx.x;
    if (idx >= (long long)KX * NP) return;
    int k = (int)(idx / NP), n = (int)(idx % NP);
    int u, g; decode_gate(n, u, g);
    float v = 0.0f;
    if (k < INSZ && u < HID) v = Wih[(g * HID + u) * 1600 + k];
    W[idx] = to_tf32(v);
}

__global__ void prep_wh1_k(const float* __restrict__ Wih, const float* __restrict__ Whh,
                           float* __restrict__ W) {
    long long idx = (long long)blockIdx.x * blockDim.x + threadIdx.x;
    if (idx >= (long long)KH1 * NP) return;
    int k = (int)(idx / NP), n = (int)(idx % NP);
    int u, g; decode_gate(n, u, g);
    float v = 0.0f;
    if (k < HID && u < HID) {
        int r = g * HID + u;
        v = Wih[r * 1600 + 600 + k] + Whh[r * HID + k];
    }
    W[idx] = to_tf32(v);
}

__global__ void prep_wc2_k(const float* __restrict__ Wih, const float* __restrict__ Whh,
                           float* __restrict__ W) {
    long long idx = (long long)blockIdx.x * blockDim.x + threadIdx.x;
    if (idx >= (long long)KCAT * NP) return;
    int k = (int)(idx / NP), n = (int)(idx % NP);
    int u, g; decode_gate(n, u, g);
    float v = 0.0f;
    if (u < HID) {
        int r = g * HID + u;
        if (k < HID) v = Wih[r * 2600 + 600 + k];
        else if (k >= 1024 && k < 1024 + HID) {
            int k2 = k - 1024;
            v = Wih[r * 2600 + 1600 + k2] + Whh[r * HID + k2];
        }
    }
    W[idx] = to_tf32(v);
}

__global__ void prep_bias_k(const float* __restrict__ bi, const float* __restrict__ bh,
                            float* __restrict__ bc) {
    int n = blockIdx.x * blockDim.x + threadIdx.x;
    if (n >= NP) return;
    int u, g; decode_gate(n, u, g);
    bc[n] = (u < HID) ? (bi[g * HID + u] + bh[g * HID + u]) : 0.0f;
}

__global__ void prep_wt1_k(const float* __restrict__ W1, float* __restrict__ W) {
    long long idx = (long long)blockIdx.x * blockDim.x + threadIdx.x;
    if (idx >= (long long)KCAT * NP) return;
    int k = (int)(idx / NP), n = (int)(idx % NP);
    float v = 0.0f;
    if (n < 4000) {
        if (k < HID) v = W1[n * 2000 + k];
        else if (k >= 1024 && k < 1024 + HID) v = W1[n * 2000 + 1000 + (k - 1024)];
    }
    W[idx] = to_tf32(v);
}

__global__ void prep_wt2_k(const float* __restrict__ W2, float* __restrict__ W) {
    long long idx = (long long)blockIdx.x * blockDim.x + threadIdx.x;
    if (idx >= (long long)NP * NP2) return;
    int k = (int)(idx / NP2), n = (int)(idx % NP2);
    float v = 0.0f;
    if (n < HID && k < 4000) v = W2[n * 4000 + k];
    W[idx] = to_tf32(v);
}

__global__ void prep_vec_k(const float* __restrict__ b, float* __restrict__ o,
                           int nreal, int ntot) {
    int n = blockIdx.x * blockDim.x + threadIdx.x;
    if (n >= ntot) return;
    o[n] = (n < nreal) ? b[n] : 0.0f;
}

__global__ void topic_k(const int* __restrict__ h, float* __restrict__ hcat) {
    int tid = blockIdx.x * blockDim.x + threadIdx.x;
    if (tid >= BATCH * 5) return;
    int b = tid / 5;
    hcat[b * KCAT + 1024 + h[tid]] = 1.0f;
}

__global__ void copy_h1_k(const float* __restrict__ h1f, float* __restrict__ hcat) {
    int idx = blockIdx.x * blockDim.x + threadIdx.x;
    if (idx >= BATCH * HID) return;
    int row = idx / HID, u = idx - row * HID;
    hcat[row * KCAT + u] = h1f[row * KCAT + u];
}

__global__ void softmax_col_k(const float* __restrict__ m, float* __restrict__ outp) {
    __shared__ float red[256];
    int col = blockIdx.x;
    int tid = threadIdx.x;
    float v = m[tid * HID + col];
    red[tid] = v;
    __syncthreads();
    for (int s = 128; s > 0; s >>= 1) {
        if (tid < s) red[tid] = fmaxf(red[tid], red[tid + s]);
        __syncthreads();
    }
    float mx = red[0];
    __syncthreads();
    float e = expf(v - mx);
    red[tid] = e;
    __syncthreads();
    for (int s = 128; s > 0; s >>= 1) {
        if (tid < s) red[tid] += red[tid + s];
        __syncthreads();
    }
    outp[tid * HID + col] = e / red[0];
}

__global__ void copy_tail_k(const float* __restrict__ h1f, const float* __restrict__ c1,
                            const float* __restrict__ h2f, const float* __restrict__ c2,
                            float* __restrict__ outp) {
    int idx = blockIdx.x * blockDim.x + threadIdx.x;
    const int SZ = BATCH * HID;
    if (idx >= 4 * SZ) return;
    int sec = idx / SZ;
    int off = idx - sec * SZ;
    int row = off / HID, u = off - row * HID;
    float v;
    if (sec == 0)      v = h1f[row * KCAT + u];
    else if (sec == 1) v = c1[off];
    else if (sec == 2) v = h2f[row * KCAT + u];
    else               v = c2[off];
    outp[idx] = v;
}

// ---------------------------------------------------------------------------
extern "C" void kernel_launch(void* const* d_in, const int* in_sizes, int n_in,
                              void* d_out, int out_size)
{
    const float* input = (const float*)d_in[0];
    const int*   hidx  = (const int*)d_in[1];
    const float* W_ih1 = (const float*)d_in[2];
    const float* W_hh1 = (const float*)d_in[3];
    const float* b_ih1 = (const float*)d_in[4];
    const float* b_hh1 = (const float*)d_in[5];
    const float* W_ih2 = (const float*)d_in[6];
    const float* W_hh2 = (const float*)d_in[7];
    const float* b_ih2 = (const float*)d_in[8];
    const float* b_hh2 = (const float*)d_in[9];
    const float* W1    = (const float*)d_in[10];
    const float* b1    = (const float*)d_in[11];
    const float* W2    = (const float*)d_in[12];
    const float* b2    = (const float*)d_in[13];
    float* outp = (float*)d_out;

    float* S = nullptr;
    cudaGetSymbolAddress((void**)&S, g_scratch);

    float* Wx1 = S + OFF_WX1;
    float* Wh1 = S + OFF_WH1;
    float* Wc2 = S + OFF_WC2;
    float* Wt1 = S + OFF_WT1;
    float* Wt2 = S + OFF_WT2;
    float* bc1 = S + OFF_BC1;
    float* bc2 = S + OFF_BC2;
    float* b1p = S + OFF_B1P;
    float* b2p = S + OFF_B2P;
    float* XP  = S + OFF_XP;
    float* zb  = S + OFF_ZB;
    float* cat[2] = { S + OFF_CAT0, S + OFF_CAT1 };
    float* c1  = S + OFF_C1;
    float* c2  = S + OFF_C2;
    float* hcat = S + OFF_HCAT;
    float* m1  = S + OFF_M1;
    float* m2  = S + OFF_M2;

    cudaFuncSetAttribute(gemm_tf32<0>, cudaFuncAttributeMaxDynamicSharedMemorySize, SMEM_BYTES);
    cudaFuncSetAttribute(gemm_tf32<1>, cudaFuncAttributeMaxDynamicSharedMemorySize, SMEM_BYTES);

    // ---- prep ----
    prep_wx1_k<<<(int)(((long long)KX * NP + 255) / 256), 256>>>(W_ih1, Wx1);
    prep_wh1_k<<<(int)(((long long)KH1 * NP + 255) / 256), 256>>>(W_ih1, W_hh1, Wh1);
    prep_wc2_k<<<(int)(((long long)KCAT * NP + 255) / 256), 256>>>(W_ih2, W_hh2, Wc2);
    prep_wt1_k<<<(int)(((long long)KCAT * NP + 255) / 256), 256>>>(W1, Wt1);
    prep_wt2_k<<<(int)(((long long)NP * NP2 + 255) / 256), 256>>>(W2, Wt2);
    prep_bias_k<<<(NP + 255) / 256, 256>>>(b_ih1, b_hh1, bc1);
    prep_bias_k<<<(NP + 255) / 256, 256>>>(b_ih2, b_hh2, bc2);
    prep_vec_k<<<(NP + 255) / 256, 256>>>(b1, b1p, 4000, NP);
    prep_vec_k<<<(NP2 + 255) / 256, 256>>>(b2, b2p, HID, NP2);
    cudaMemsetAsync(S + OFF_ZB, 0, (size_t)ZERO_CNT * sizeof(float), 0);

    dim3 blk(256);
    dim3 gridXP(NP / BN, (BATCH * TSTEPS) / BM);  // 63 x 128
    dim3 gridG (NP / BN, BATCH / BM);             // 63 x 2
    dim3 gridL2(NP2 / BN, BATCH / BM);            // 16 x 2

    // ---- XP = X @ Wx1 (parallel over all T) ----
    gemm_tf32<0><<<gridXP, blk, SMEM_BYTES>>>(
        input, INSZ, INSZ, KX, Wx1, NP, zb, nullptr, 0,
        XP, NP, NP, nullptr, nullptr, 0);

    // ---- sequential scan ----
    int cur = 0;
    for (int t = 0; t < TSTEPS; t++) {
        int nxt = cur ^ 1;
        // LSTM1: gates = h1_old @ Wh1 + XP[t] + bc1
        gemm_tf32<1><<<gridG, blk, SMEM_BYTES>>>(
            cat[cur], KCAT, KH1, KH1, Wh1, NP, bc1,
            XP + (size_t)t * NP, LD_XP,
            nullptr, 0, 0, c1, cat[nxt], KCAT);
        // LSTM2: gates = [h1_new | h2_old] @ Wc2 + bc2
        gemm_tf32<1><<<gridG, blk, SMEM_BYTES>>>(
            cat[nxt], KCAT, KCAT, KCAT, Wc2, NP, bc2,
            nullptr, 0,
            nullptr, 0, 0, c2, cat[cur] + 1024, KCAT);
        cur = nxt;
    }
    float* h1f = cat[cur];            // h1 at cols [0,1000)
    float* h2f = cat[cur ^ 1] + 1024; // h2 at cols [1024,2024) of other buf

    // ---- head ----
    topic_k<<<(BATCH * 5 + 255) / 256, 256>>>(hidx, hcat);
    copy_h1_k<<<(BATCH * HID + 255) / 256, 256>>>(h1f, hcat);
    gemm_tf32<0><<<gridG, blk, SMEM_BYTES>>>(
        hcat, KCAT, KCAT, KCAT, Wt1, NP, b1p, nullptr, 0,
        m1, NP, NP, nullptr, nullptr, 0);
    gemm_tf32<0><<<gridL2, blk, SMEM_BYTES>>>(
        m1, NP, NP, NP, Wt2, NP2, b2p, nullptr, 0,
        m2, HID, HID, nullptr, nullptr, 0);
    softmax_col_k<<<HID, 256>>>(m2, outp);

    if (out_size >= 5 * BATCH * HID) {
        copy_tail_k<<<(4 * BATCH * HID + 255) / 256, 256>>>(
            h1f, c1, h2f, c2, outp + BATCH * HID);
    }
}